// round 1
// baseline (speedup 1.0000x reference)
#include <cuda_runtime.h>
#include <cuda_bf16.h>
#include <cstdint>

// Problem constants
#define SEQ  2048
#define HID  1024
#define NH   16
#define HD   64
#define QKVN (3 * HID)   // 3072

// Scratch (allocation-free rule: __device__ globals)
__device__ float g_qkv[SEQ * QKVN];   // [2048, 3072]
__device__ float g_attn[SEQ * HID];   // [2048, 1024]

// ---------------------------------------------------------------------------
// SGEMM with bias: C[M,N] = A[M,K] @ B[K,N] + bias[N]
// 128x128 tile, BK=8, 256 threads, 8x8 per thread. All dims divisible.
// ---------------------------------------------------------------------------
__global__ __launch_bounds__(256) void sgemm_bias(
    const float* __restrict__ A, const float* __restrict__ B,
    const float* __restrict__ bias, float* __restrict__ C,
    int M, int N, int K)
{
    __shared__ float As[8][128];
    __shared__ float Bs[8][128];

    const int tid = threadIdx.x;
    const int tx = tid & 15;          // 0..15  (cols)
    const int ty = tid >> 4;          // 0..15  (rows)
    const int row0 = blockIdx.y * 128;
    const int col0 = blockIdx.x * 128;

    // global load mapping
    const int rowA = tid >> 1;              // 0..127
    const int colA = (tid & 1) * 4;         // 0 or 4
    const int rowB = tid >> 5;              // 0..7
    const int colB = (tid & 31) * 4;        // 0..124

    const float* Ap = A + (size_t)(row0 + rowA) * K + colA;
    const float* Bp = B + (size_t)rowB * N + col0 + colB;

    float acc[8][8];
#pragma unroll
    for (int i = 0; i < 8; i++)
#pragma unroll
        for (int j = 0; j < 8; j++) acc[i][j] = 0.f;

    for (int k0 = 0; k0 < K; k0 += 8) {
        float4 a4 = *(const float4*)(Ap + k0);
        float4 b4 = *(const float4*)(Bp + (size_t)k0 * N);
        As[colA + 0][rowA] = a4.x;
        As[colA + 1][rowA] = a4.y;
        As[colA + 2][rowA] = a4.z;
        As[colA + 3][rowA] = a4.w;
        *(float4*)&Bs[rowB][colB] = b4;
        __syncthreads();

#pragma unroll
        for (int kk = 0; kk < 8; kk++) {
            float4 a0 = *(const float4*)&As[kk][ty * 8];
            float4 a1 = *(const float4*)&As[kk][ty * 8 + 4];
            float4 b0 = *(const float4*)&Bs[kk][tx * 8];
            float4 b1 = *(const float4*)&Bs[kk][tx * 8 + 4];
            float ar[8] = {a0.x, a0.y, a0.z, a0.w, a1.x, a1.y, a1.z, a1.w};
            float br[8] = {b0.x, b0.y, b0.z, b0.w, b1.x, b1.y, b1.z, b1.w};
#pragma unroll
            for (int i = 0; i < 8; i++)
#pragma unroll
                for (int j = 0; j < 8; j++)
                    acc[i][j] = fmaf(ar[i], br[j], acc[i][j]);
        }
        __syncthreads();
    }

    // epilogue with bias
#pragma unroll
    for (int i = 0; i < 8; i++) {
        size_t r = (size_t)(row0 + ty * 8 + i);
#pragma unroll
        for (int j = 0; j < 8; j += 4) {
            int c = col0 + tx * 8 + j;
            float4 o;
            o.x = acc[i][j + 0] + bias[c + 0];
            o.y = acc[i][j + 1] + bias[c + 1];
            o.z = acc[i][j + 2] + bias[c + 2];
            o.w = acc[i][j + 3] + bias[c + 3];
            *(float4*)(C + r * N + c) = o;
        }
    }
}

// ---------------------------------------------------------------------------
// Flash attention, causal. One CTA = (head, 128-row q block). 256 threads.
// Q/K in smem d-major [64][132] (pad->float4-aligned, conflict-free reads).
// P tile aliases the K tile region ([128][132]). V is [128][64] row-major.
// Online softmax with per-row (m, l) replicated across the 16 tx threads.
// ---------------------------------------------------------------------------
#define LDP 132
#define ATTN_SMEM_FLOATS (64 * LDP + 128 * LDP + 128 * 64)
#define ATTN_SMEM_BYTES  (ATTN_SMEM_FLOATS * 4)

__global__ __launch_bounds__(256) void attn_kernel(
    const float* __restrict__ qkv, float* __restrict__ out)
{
    extern __shared__ float sm[];
    float* Qs  = sm;                       // [64][132]  d-major
    float* KPs = sm + 64 * LDP;            // Ks [64][132] d-major, later Ps [128][132]
    float* Vs  = sm + 64 * LDP + 128 * LDP;// [128][64]

    const int tid = threadIdx.x;
    const int tx = tid & 15;   // score cols / d cols
    const int ty = tid >> 4;   // q rows
    const int h  = blockIdx.y;
    const int qb = (int)gridDim.x - 1 - (int)blockIdx.x;  // heavy CTAs first
    const int q0 = qb * 128;

    // Load Q tile transposed (d-major), pre-scaled by 1/sqrt(64)=0.125
    {
        const int q = tid >> 1;
        const int dbase = (tid & 1) * 32;
        const float* src = qkv + (size_t)(q0 + q) * QKVN + h * HD;
#pragma unroll
        for (int u = 0; u < 8; u++) {
            int d = dbase + u * 4;
            float4 v = *(const float4*)(src + d);
            Qs[(d + 0) * LDP + q] = v.x * 0.125f;
            Qs[(d + 1) * LDP + q] = v.y * 0.125f;
            Qs[(d + 2) * LDP + q] = v.z * 0.125f;
            Qs[(d + 3) * LDP + q] = v.w * 0.125f;
        }
    }

    float O[8][4];
    float m[8], l[8];
#pragma unroll
    for (int i = 0; i < 8; i++) {
        m[i] = -1e30f; l[i] = 0.f;
#pragma unroll
        for (int dd = 0; dd < 4; dd++) O[i][dd] = 0.f;
    }

    for (int kb = 0; kb <= qb; kb++) {
        __syncthreads();  // previous iteration readers of KPs/Vs done (also orders Q writes @kb=0)

        // Load K tile transposed (d-major)
        {
            const int k = tid >> 1;
            const int dbase = (tid & 1) * 32;
            const float* src = qkv + (size_t)(kb * 128 + k) * QKVN + HID + h * HD;
#pragma unroll
            for (int u = 0; u < 8; u++) {
                int d = dbase + u * 4;
                float4 v = *(const float4*)(src + d);
                KPs[(d + 0) * LDP + k] = v.x;
                KPs[(d + 1) * LDP + k] = v.y;
                KPs[(d + 2) * LDP + k] = v.z;
                KPs[(d + 3) * LDP + k] = v.w;
            }
        }
        // Load V tile row-major [c][d]
        {
#pragma unroll
            for (int u = 0; u < 8; u++) {
                int i4 = u * 256 + tid;       // float4 index 0..2047
                int c = i4 >> 4;
                int d = (i4 & 15) * 4;
                float4 v = *(const float4*)(qkv + (size_t)(kb * 128 + c) * QKVN + 2 * HID + h * HD + d);
                *(float4*)&Vs[c * 64 + d] = v;
            }
        }
        __syncthreads();

        // scores S[8][8]: rows q = ty*8+i, cols k = tx*8+j
        float S[8][8];
#pragma unroll
        for (int i = 0; i < 8; i++)
#pragma unroll
            for (int j = 0; j < 8; j++) S[i][j] = 0.f;

#pragma unroll 4
        for (int d = 0; d < 64; d++) {
            float4 aq0 = *(const float4*)&Qs[d * LDP + ty * 8];
            float4 aq1 = *(const float4*)&Qs[d * LDP + ty * 8 + 4];
            float4 ak0 = *(const float4*)&KPs[d * LDP + tx * 8];
            float4 ak1 = *(const float4*)&KPs[d * LDP + tx * 8 + 4];
            float aq[8] = {aq0.x, aq0.y, aq0.z, aq0.w, aq1.x, aq1.y, aq1.z, aq1.w};
            float ak[8] = {ak0.x, ak0.y, ak0.z, ak0.w, ak1.x, ak1.y, ak1.z, ak1.w};
#pragma unroll
            for (int i = 0; i < 8; i++)
#pragma unroll
                for (int j = 0; j < 8; j++)
                    S[i][j] = fmaf(aq[i], ak[j], S[i][j]);
        }

        // causal mask on the diagonal block
        if (kb == qb) {
#pragma unroll
            for (int i = 0; i < 8; i++) {
                int qg = ty * 8 + i;
#pragma unroll
                for (int j = 0; j < 8; j++) {
                    int kg = tx * 8 + j;
                    if (kg > qg) S[i][j] = -1e30f;
                }
            }
        }

        // online softmax update (16-lane groups share a row; consecutive lanes)
#pragma unroll
        for (int i = 0; i < 8; i++) {
            float mt = S[i][0];
#pragma unroll
            for (int j = 1; j < 8; j++) mt = fmaxf(mt, S[i][j]);
            mt = fmaxf(mt, __shfl_xor_sync(0xffffffffu, mt, 1));
            mt = fmaxf(mt, __shfl_xor_sync(0xffffffffu, mt, 2));
            mt = fmaxf(mt, __shfl_xor_sync(0xffffffffu, mt, 4));
            mt = fmaxf(mt, __shfl_xor_sync(0xffffffffu, mt, 8));
            float mnew = fmaxf(m[i], mt);
            float alpha = __expf(m[i] - mnew);
            float ps = 0.f;
#pragma unroll
            for (int j = 0; j < 8; j++) {
                float p = __expf(S[i][j] - mnew);
                S[i][j] = p;
                ps += p;
            }
            ps += __shfl_xor_sync(0xffffffffu, ps, 1);
            ps += __shfl_xor_sync(0xffffffffu, ps, 2);
            ps += __shfl_xor_sync(0xffffffffu, ps, 4);
            ps += __shfl_xor_sync(0xffffffffu, ps, 8);
            l[i] = l[i] * alpha + ps;
            m[i] = mnew;
#pragma unroll
            for (int dd = 0; dd < 4; dd++) O[i][dd] *= alpha;
        }

        __syncthreads();  // all threads done reading Ks before P overwrite

        // write P row-major into KPs: Ps[q][c], q = ty*8+i, c = tx*8+j
#pragma unroll
        for (int i = 0; i < 8; i++) {
            float4 p0 = make_float4(S[i][0], S[i][1], S[i][2], S[i][3]);
            float4 p1 = make_float4(S[i][4], S[i][5], S[i][6], S[i][7]);
            *(float4*)&KPs[(ty * 8 + i) * LDP + tx * 8] = p0;
            *(float4*)&KPs[(ty * 8 + i) * LDP + tx * 8 + 4] = p1;
        }
        __syncthreads();

        // O += P @ V : thread owns q rows ty*8+i, d cols tx*4..tx*4+3
#pragma unroll 2
        for (int c = 0; c < 128; c++) {
            float4 av = *(const float4*)&Vs[c * 64 + tx * 4];
#pragma unroll
            for (int i = 0; i < 8; i++) {
                float p = KPs[(ty * 8 + i) * LDP + c];  // broadcast load
                O[i][0] = fmaf(p, av.x, O[i][0]);
                O[i][1] = fmaf(p, av.y, O[i][1]);
                O[i][2] = fmaf(p, av.z, O[i][2]);
                O[i][3] = fmaf(p, av.w, O[i][3]);
            }
        }
    }

    // epilogue: normalize by l, write [q][h*64 + d]
#pragma unroll
    for (int i = 0; i < 8; i++) {
        float inv = 1.0f / l[i];
        float4 o = make_float4(O[i][0] * inv, O[i][1] * inv, O[i][2] * inv, O[i][3] * inv);
        *(float4*)(out + (size_t)(q0 + ty * 8 + i) * HID + h * HD + tx * 4) = o;
    }
}

// ---------------------------------------------------------------------------
// Launch
// ---------------------------------------------------------------------------
extern "C" void kernel_launch(void* const* d_in, const int* in_sizes, int n_in,
                              void* d_out, int out_size)
{
    const float* x      = (const float*)d_in[0];
    const float* w_attn = (const float*)d_in[1];
    const float* b_attn = (const float*)d_in[2];
    const float* w_proj = (const float*)d_in[3];
    const float* b_proj = (const float*)d_in[4];
    float* out = (float*)d_out;

    float *qkv_p = nullptr, *attn_p = nullptr;
    cudaGetSymbolAddress((void**)&qkv_p,  g_qkv);
    cudaGetSymbolAddress((void**)&attn_p, g_attn);

    cudaFuncSetAttribute(attn_kernel,
                         cudaFuncAttributeMaxDynamicSharedMemorySize,
                         ATTN_SMEM_BYTES);

    // 1) QKV = X @ W_attn + b_attn        [2048, 3072]
    sgemm_bias<<<dim3(QKVN / 128, SEQ / 128), 256>>>(
        x, w_attn, b_attn, qkv_p, SEQ, QKVN, HID);

    // 2) causal flash attention -> g_attn [2048, 1024]
    attn_kernel<<<dim3(SEQ / 128, NH), 256, ATTN_SMEM_BYTES>>>(qkv_p, attn_p);

    // 3) out = attn @ W_proj + b_proj     [2048, 1024]
    sgemm_bias<<<dim3(HID / 128, SEQ / 128), 256>>>(
        attn_p, w_proj, b_proj, out, SEQ, HID, HID);
}

// round 3
// speedup vs baseline: 1.6238x; 1.6238x over previous
#include <cuda_runtime.h>
#include <cuda_bf16.h>
#include <cstdint>

// Problem constants
#define SEQ  2048
#define HID  1024
#define NH   16
#define HD   64
#define QKVN (3 * HID)   // 3072

// Scratch (allocation-free rule: __device__ globals)
__device__ float g_qkv[SEQ * QKVN];        // [2048, 3072]
__device__ float g_attn[SEQ * HID];        // [2048, 1024]
__device__ float g_wattnT[QKVN * HID];     // [3072, 1024]  w_attn^T
__device__ float g_wprojT[HID * HID];      // [1024, 1024]  w_proj^T

// ===========================================================================
// Helpers
// ===========================================================================
__device__ __forceinline__ uint32_t smem_u32(const void* p) {
    uint32_t a;
    asm("{ .reg .u64 t; cvta.to.shared.u64 t, %1; cvt.u32.u64 %0, t; }" : "=r"(a) : "l"(p));
    return a;
}
__device__ __forceinline__ uint32_t f2tf32(float v) {
    uint32_t r;
    asm("cvt.rna.tf32.f32 %0, %1;" : "=r"(r) : "f"(v));
    return r;
}
__device__ __forceinline__ void mma_tf32(float d[4],
                                         uint32_t a0, uint32_t a1, uint32_t a2, uint32_t a3,
                                         uint32_t b0, uint32_t b1) {
    asm volatile(
        "mma.sync.aligned.m16n8k8.row.col.f32.tf32.tf32.f32 "
        "{%0,%1,%2,%3}, {%4,%5,%6,%7}, {%8,%9}, {%0,%1,%2,%3};"
        : "+f"(d[0]), "+f"(d[1]), "+f"(d[2]), "+f"(d[3])
        : "r"(a0), "r"(a1), "r"(a2), "r"(a3), "r"(b0), "r"(b1));
}
#define CP_ASYNC16(dst_u32, src_ptr) \
    asm volatile("cp.async.cg.shared.global [%0], [%1], 16;" :: "r"(dst_u32), "l"(src_ptr))
#define CP_COMMIT() asm volatile("cp.async.commit_group;" ::: "memory")
#define CP_WAIT1()  asm volatile("cp.async.wait_group 1;" ::: "memory")
#define CP_WAIT0()  asm volatile("cp.async.wait_group 0;" ::: "memory")

// ===========================================================================
// Weight transpose: out[n][k] = in[k][n]
// ===========================================================================
__global__ __launch_bounds__(256) void transpose_k(
    const float* __restrict__ in, float* __restrict__ out, int K, int N)
{
    __shared__ float tile[32][33];
    int n0 = blockIdx.x * 32, k0 = blockIdx.y * 32;
    int tx = threadIdx.x & 31, ty = threadIdx.x >> 5;  // 32 x 8
#pragma unroll
    for (int i = 0; i < 32; i += 8)
        tile[ty + i][tx] = in[(size_t)(k0 + ty + i) * N + n0 + tx];
    __syncthreads();
#pragma unroll
    for (int i = 0; i < 32; i += 8)
        out[(size_t)(n0 + ty + i) * K + k0 + tx] = tile[tx][ty + i];
}

// ===========================================================================
// tf32 mma.sync GEMM: C[M,N] = A[M,K] @ BT[N,K]^T + bias[N]
// CTA tile 128x128, BK=32, 256 threads (8 warps as 2x4), warp tile 64x32.
// cp.async double-buffered smem. A smem [128][36], BT smem [128][36].
// ===========================================================================
#define LDK 36
#define TILE_FLOATS (128 * LDK)              // per matrix per buffer
#define GEMM_SMEM (4 * TILE_FLOATS * 4)      // A0,A1,B0,B1

__global__ __launch_bounds__(256)
void gemm_tf32(const float* __restrict__ A, const float* __restrict__ BT,
               const float* __restrict__ bias, float* __restrict__ C,
               int M, int N, int K)
{
    extern __shared__ float smem[];
    float* As = smem;                         // [2][128*LDK]
    float* Bs = smem + 2 * TILE_FLOATS;       // [2][128*LDK]
    const uint32_t as_u32 = smem_u32(As);
    const uint32_t bs_u32 = smem_u32(Bs);

    const int tid  = threadIdx.x;
    const int wid  = tid >> 5;
    const int lane = tid & 31;
    const int g = lane >> 2;                  // group 0..7
    const int t = lane & 3;                   // thread-in-group 0..3
    const int wy = wid >> 2;                  // 0..1 (m)
    const int wx = wid & 3;                   // 0..3 (n)
    const int row0 = blockIdx.y * 128;
    const int col0 = blockIdx.x * 128;
    const int NS = K >> 5;                    // stages of BK=32

    // copy mapping: 128 rows x 8 float4 = 1024 float4 per matrix; 4 per thread
    const int crow = tid >> 1;                // two threads per row? no: see below
    // use idx = u*256 + tid; row = idx>>3 (0..127), c4 = idx&7
    const float* Ag = A  + (size_t)row0 * K;
    const float* Bg = BT + (size_t)col0 * K;

    auto copy_stage = [&](int s, int buf) {
        const int k0 = s * 32;
#pragma unroll
        for (int u = 0; u < 4; u++) {
            int idx = u * 256 + tid;
            int row = idx >> 3;
            int c4  = idx & 7;
            uint32_t doff = (uint32_t)((row * LDK + c4 * 4) * 4);
            CP_ASYNC16(as_u32 + buf * (TILE_FLOATS * 4) + doff,
                       Ag + (size_t)row * K + k0 + c4 * 4);
            CP_ASYNC16(bs_u32 + buf * (TILE_FLOATS * 4) + doff,
                       Bg + (size_t)row * K + k0 + c4 * 4);
        }
    };
    (void)crow;

    float acc[4][4][4];
#pragma unroll
    for (int mt = 0; mt < 4; mt++)
#pragma unroll
        for (int nt = 0; nt < 4; nt++)
#pragma unroll
            for (int r = 0; r < 4; r++) acc[mt][nt][r] = 0.f;

    // prologue
    copy_stage(0, 0);
    CP_COMMIT();

    for (int s = 0; s < NS; s++) {
        const int buf = s & 1;
        if (s + 1 < NS) {
            copy_stage(s + 1, buf ^ 1);
            CP_COMMIT();
            CP_WAIT1();
        } else {
            CP_WAIT0();
        }
        __syncthreads();

        const float* Ab = As + buf * TILE_FLOATS;
        const float* Bb = Bs + buf * TILE_FLOATS;

#pragma unroll
        for (int ks = 0; ks < 4; ks++) {
            const int kk = ks * 8 + t;
            uint32_t af[4][4];
#pragma unroll
            for (int mt = 0; mt < 4; mt++) {
                const float* pa = Ab + (wy * 64 + mt * 16 + g) * LDK + kk;
                af[mt][0] = f2tf32(pa[0]);
                af[mt][1] = f2tf32(pa[8 * LDK]);
                af[mt][2] = f2tf32(pa[4]);
                af[mt][3] = f2tf32(pa[8 * LDK + 4]);
            }
            uint32_t bf[4][2];
#pragma unroll
            for (int nt = 0; nt < 4; nt++) {
                const float* pb = Bb + (wx * 32 + nt * 8 + g) * LDK + kk;
                bf[nt][0] = f2tf32(pb[0]);
                bf[nt][1] = f2tf32(pb[4]);
            }
#pragma unroll
            for (int mt = 0; mt < 4; mt++)
#pragma unroll
                for (int nt = 0; nt < 4; nt++)
                    mma_tf32(acc[mt][nt], af[mt][0], af[mt][1], af[mt][2], af[mt][3],
                             bf[nt][0], bf[nt][1]);
        }
        __syncthreads();   // compute done before next-next copy overwrites buf
    }

    // epilogue with bias. c0,c1 at (row=g, col=2t,2t+1); c2,c3 at row=g+8.
#pragma unroll
    for (int mt = 0; mt < 4; mt++) {
        int m = row0 + wy * 64 + mt * 16 + g;
#pragma unroll
        for (int nt = 0; nt < 4; nt++) {
            int n = col0 + wx * 32 + nt * 8 + 2 * t;
            float2 o0, o1;
            o0.x = acc[mt][nt][0] + bias[n];
            o0.y = acc[mt][nt][1] + bias[n + 1];
            o1.x = acc[mt][nt][2] + bias[n];
            o1.y = acc[mt][nt][3] + bias[n + 1];
            *(float2*)(C + (size_t)m * N + n)       = o0;
            *(float2*)(C + (size_t)(m + 8) * N + n) = o1;
        }
    }
}

// ---------------------------------------------------------------------------
// Flash attention, causal (unchanged). One CTA = (head, 128 q rows).
// ---------------------------------------------------------------------------
#define LDP 132
#define ATTN_SMEM_FLOATS (64 * LDP + 128 * LDP + 128 * 64)
#define ATTN_SMEM_BYTES  (ATTN_SMEM_FLOATS * 4)

__global__ __launch_bounds__(256) void attn_kernel(
    const float* __restrict__ qkv, float* __restrict__ out)
{
    extern __shared__ float sm[];
    float* Qs  = sm;                        // [64][132]  d-major
    float* KPs = sm + 64 * LDP;             // Ks [64][132] d-major, later Ps [128][132]
    float* Vs  = sm + 64 * LDP + 128 * LDP; // [128][64]

    const int tid = threadIdx.x;
    const int tx = tid & 15;
    const int ty = tid >> 4;
    const int h  = blockIdx.y;
    const int qb = (int)gridDim.x - 1 - (int)blockIdx.x;
    const int q0 = qb * 128;

    {
        const int q = tid >> 1;
        const int dbase = (tid & 1) * 32;
        const float* src = qkv + (size_t)(q0 + q) * QKVN + h * HD;
#pragma unroll
        for (int u = 0; u < 8; u++) {
            int d = dbase + u * 4;
            float4 v = *(const float4*)(src + d);
            Qs[(d + 0) * LDP + q] = v.x * 0.125f;
            Qs[(d + 1) * LDP + q] = v.y * 0.125f;
            Qs[(d + 2) * LDP + q] = v.z * 0.125f;
            Qs[(d + 3) * LDP + q] = v.w * 0.125f;
        }
    }

    float O[8][4];
    float m[8], l[8];
#pragma unroll
    for (int i = 0; i < 8; i++) {
        m[i] = -1e30f; l[i] = 0.f;
#pragma unroll
        for (int dd = 0; dd < 4; dd++) O[i][dd] = 0.f;
    }

    for (int kb = 0; kb <= qb; kb++) {
        __syncthreads();

        {
            const int k = tid >> 1;
            const int dbase = (tid & 1) * 32;
            const float* src = qkv + (size_t)(kb * 128 + k) * QKVN + HID + h * HD;
#pragma unroll
            for (int u = 0; u < 8; u++) {
                int d = dbase + u * 4;
                float4 v = *(const float4*)(src + d);
                KPs[(d + 0) * LDP + k] = v.x;
                KPs[(d + 1) * LDP + k] = v.y;
                KPs[(d + 2) * LDP + k] = v.z;
                KPs[(d + 3) * LDP + k] = v.w;
            }
        }
        {
#pragma unroll
            for (int u = 0; u < 8; u++) {
                int i4 = u * 256 + tid;
                int c = i4 >> 4;
                int d = (i4 & 15) * 4;
                float4 v = *(const float4*)(qkv + (size_t)(kb * 128 + c) * QKVN + 2 * HID + h * HD + d);
                *(float4*)&Vs[c * 64 + d] = v;
            }
        }
        __syncthreads();

        float S[8][8];
#pragma unroll
        for (int i = 0; i < 8; i++)
#pragma unroll
            for (int j = 0; j < 8; j++) S[i][j] = 0.f;

#pragma unroll 4
        for (int d = 0; d < 64; d++) {
            float4 aq0 = *(const float4*)&Qs[d * LDP + ty * 8];
            float4 aq1 = *(const float4*)&Qs[d * LDP + ty * 8 + 4];
            float4 ak0 = *(const float4*)&KPs[d * LDP + tx * 8];
            float4 ak1 = *(const float4*)&KPs[d * LDP + tx * 8 + 4];
            float aq[8] = {aq0.x, aq0.y, aq0.z, aq0.w, aq1.x, aq1.y, aq1.z, aq1.w};
            float ak[8] = {ak0.x, ak0.y, ak0.z, ak0.w, ak1.x, ak1.y, ak1.z, ak1.w};
#pragma unroll
            for (int i = 0; i < 8; i++)
#pragma unroll
                for (int j = 0; j < 8; j++)
                    S[i][j] = fmaf(aq[i], ak[j], S[i][j]);
        }

        if (kb == qb) {
#pragma unroll
            for (int i = 0; i < 8; i++) {
                int qg = ty * 8 + i;
#pragma unroll
                for (int j = 0; j < 8; j++) {
                    int kg = tx * 8 + j;
                    if (kg > qg) S[i][j] = -1e30f;
                }
            }
        }

#pragma unroll
        for (int i = 0; i < 8; i++) {
            float mt = S[i][0];
#pragma unroll
            for (int j = 1; j < 8; j++) mt = fmaxf(mt, S[i][j]);
            mt = fmaxf(mt, __shfl_xor_sync(0xffffffffu, mt, 1));
            mt = fmaxf(mt, __shfl_xor_sync(0xffffffffu, mt, 2));
            mt = fmaxf(mt, __shfl_xor_sync(0xffffffffu, mt, 4));
            mt = fmaxf(mt, __shfl_xor_sync(0xffffffffu, mt, 8));
            float mnew = fmaxf(m[i], mt);
            float alpha = __expf(m[i] - mnew);
            float ps = 0.f;
#pragma unroll
            for (int j = 0; j < 8; j++) {
                float p = __expf(S[i][j] - mnew);
                S[i][j] = p;
                ps += p;
            }
            ps += __shfl_xor_sync(0xffffffffu, ps, 1);
            ps += __shfl_xor_sync(0xffffffffu, ps, 2);
            ps += __shfl_xor_sync(0xffffffffu, ps, 4);
            ps += __shfl_xor_sync(0xffffffffu, ps, 8);
            l[i] = l[i] * alpha + ps;
            m[i] = mnew;
#pragma unroll
            for (int dd = 0; dd < 4; dd++) O[i][dd] *= alpha;
        }

        __syncthreads();

#pragma unroll
        for (int i = 0; i < 8; i++) {
            float4 p0 = make_float4(S[i][0], S[i][1], S[i][2], S[i][3]);
            float4 p1 = make_float4(S[i][4], S[i][5], S[i][6], S[i][7]);
            *(float4*)&KPs[(ty * 8 + i) * LDP + tx * 8] = p0;
            *(float4*)&KPs[(ty * 8 + i) * LDP + tx * 8 + 4] = p1;
        }
        __syncthreads();

#pragma unroll 2
        for (int c = 0; c < 128; c++) {
            float4 av = *(const float4*)&Vs[c * 64 + tx * 4];
#pragma unroll
            for (int i = 0; i < 8; i++) {
                float p = KPs[(ty * 8 + i) * LDP + c];
                O[i][0] = fmaf(p, av.x, O[i][0]);
                O[i][1] = fmaf(p, av.y, O[i][1]);
                O[i][2] = fmaf(p, av.z, O[i][2]);
                O[i][3] = fmaf(p, av.w, O[i][3]);
            }
        }
    }

#pragma unroll
    for (int i = 0; i < 8; i++) {
        float inv = 1.0f / l[i];
        float4 o = make_float4(O[i][0] * inv, O[i][1] * inv, O[i][2] * inv, O[i][3] * inv);
        *(float4*)(out + (size_t)(q0 + ty * 8 + i) * HID + h * HD + tx * 4) = o;
    }
}

// ---------------------------------------------------------------------------
// Launch
// ---------------------------------------------------------------------------
extern "C" void kernel_launch(void* const* d_in, const int* in_sizes, int n_in,
                              void* d_out, int out_size)
{
    const float* x      = (const float*)d_in[0];
    const float* w_attn = (const float*)d_in[1];
    const float* b_attn = (const float*)d_in[2];
    const float* w_proj = (const float*)d_in[3];
    const float* b_proj = (const float*)d_in[4];
    float* out = (float*)d_out;

    float *qkv_p, *attn_p, *wattnT_p, *wprojT_p;
    cudaGetSymbolAddress((void**)&qkv_p,    g_qkv);
    cudaGetSymbolAddress((void**)&attn_p,   g_attn);
    cudaGetSymbolAddress((void**)&wattnT_p, g_wattnT);
    cudaGetSymbolAddress((void**)&wprojT_p, g_wprojT);

    cudaFuncSetAttribute(attn_kernel,
                         cudaFuncAttributeMaxDynamicSharedMemorySize, ATTN_SMEM_BYTES);
    cudaFuncSetAttribute(gemm_tf32,
                         cudaFuncAttributeMaxDynamicSharedMemorySize, GEMM_SMEM);

    // 0) transpose weights -> K-major operands
    transpose_k<<<dim3(QKVN / 32, HID / 32), 256>>>(w_attn, wattnT_p, HID, QKVN);
    transpose_k<<<dim3(HID / 32, HID / 32), 256>>>(w_proj, wprojT_p, HID, HID);

    // 1) QKV = X @ W_attn + b_attn        [2048, 3072]   (tf32 mma.sync)
    gemm_tf32<<<dim3(QKVN / 128, SEQ / 128), 256, GEMM_SMEM>>>(
        x, wattnT_p, b_attn, qkv_p, SEQ, QKVN, HID);

    // 2) causal flash attention -> g_attn [2048, 1024]
    attn_kernel<<<dim3(SEQ / 128, NH), 256, ATTN_SMEM_BYTES>>>(qkv_p, attn_p);

    // 3) out = attn @ W_proj + b_proj     [2048, 1024]   (tf32 mma.sync)
    gemm_tf32<<<dim3(HID / 128, SEQ / 128), 256, GEMM_SMEM>>>(
        attn_p, wprojT_p, b_proj, out, SEQ, HID, HID);
}

// round 4
// speedup vs baseline: 3.1181x; 1.9202x over previous
#include <cuda_runtime.h>
#include <cuda_bf16.h>
#include <cstdint>

// Problem constants
#define SEQ  2048
#define HID  1024
#define NH   16
#define HD   64
#define QKVN (3 * HID)   // 3072

// Scratch (allocation-free rule: __device__ globals)
__device__ float g_qkv[SEQ * QKVN];        // [2048, 3072]
__device__ float g_attn[SEQ * HID];        // [2048, 1024]
__device__ float g_wattnT[QKVN * HID];     // [3072, 1024]  w_attn^T
__device__ float g_wprojT[HID * HID];      // [1024, 1024]  w_proj^T

// ===========================================================================
// Helpers
// ===========================================================================
__device__ __forceinline__ uint32_t smem_u32(const void* p) {
    uint32_t a;
    asm("{ .reg .u64 t; cvta.to.shared.u64 t, %1; cvt.u32.u64 %0, t; }" : "=r"(a) : "l"(p));
    return a;
}
__device__ __forceinline__ uint32_t f2tf32(float v) {
    uint32_t r;
    asm("cvt.rna.tf32.f32 %0, %1;" : "=r"(r) : "f"(v));
    return r;
}
__device__ __forceinline__ float tf32v(float v) {        // tf32-rounded float value
    return __uint_as_float(f2tf32(v));
}
__device__ __forceinline__ void mma_tf32(float d[4],
                                         uint32_t a0, uint32_t a1, uint32_t a2, uint32_t a3,
                                         uint32_t b0, uint32_t b1) {
    asm volatile(
        "mma.sync.aligned.m16n8k8.row.col.f32.tf32.tf32.f32 "
        "{%0,%1,%2,%3}, {%4,%5,%6,%7}, {%8,%9}, {%0,%1,%2,%3};"
        : "+f"(d[0]), "+f"(d[1]), "+f"(d[2]), "+f"(d[3])
        : "r"(a0), "r"(a1), "r"(a2), "r"(a3), "r"(b0), "r"(b1));
}
#define CP_ASYNC16(dst_u32, src_ptr) \
    asm volatile("cp.async.cg.shared.global [%0], [%1], 16;" :: "r"(dst_u32), "l"(src_ptr))
#define CP_COMMIT() asm volatile("cp.async.commit_group;" ::: "memory")
#define CP_WAIT1()  asm volatile("cp.async.wait_group 1;" ::: "memory")
#define CP_WAIT0()  asm volatile("cp.async.wait_group 0;" ::: "memory")

// ===========================================================================
// Weight transpose: out[n][k] = in[k][n]
// ===========================================================================
__global__ __launch_bounds__(256) void transpose_k(
    const float* __restrict__ in, float* __restrict__ out, int K, int N)
{
    __shared__ float tile[32][33];
    int n0 = blockIdx.x * 32, k0 = blockIdx.y * 32;
    int tx = threadIdx.x & 31, ty = threadIdx.x >> 5;  // 32 x 8
#pragma unroll
    for (int i = 0; i < 32; i += 8)
        tile[ty + i][tx] = in[(size_t)(k0 + ty + i) * N + n0 + tx];
    __syncthreads();
#pragma unroll
    for (int i = 0; i < 32; i += 8)
        out[(size_t)(n0 + ty + i) * K + k0 + tx] = tile[tx][ty + i];
}

// ===========================================================================
// tf32 mma.sync GEMM (unchanged from R3): C = A @ BT^T + bias
// ===========================================================================
#define LDK 36
#define TILE_FLOATS (128 * LDK)
#define GEMM_SMEM (4 * TILE_FLOATS * 4)

__global__ __launch_bounds__(256)
void gemm_tf32(const float* __restrict__ A, const float* __restrict__ BT,
               const float* __restrict__ bias, float* __restrict__ C,
               int M, int N, int K)
{
    extern __shared__ float smem[];
    float* As = smem;
    float* Bs = smem + 2 * TILE_FLOATS;
    const uint32_t as_u32 = smem_u32(As);
    const uint32_t bs_u32 = smem_u32(Bs);

    const int tid  = threadIdx.x;
    const int wid  = tid >> 5;
    const int lane = tid & 31;
    const int g = lane >> 2;
    const int t = lane & 3;
    const int wy = wid >> 2;
    const int wx = wid & 3;
    const int row0 = blockIdx.y * 128;
    const int col0 = blockIdx.x * 128;
    const int NS = K >> 5;

    const float* Ag = A  + (size_t)row0 * K;
    const float* Bg = BT + (size_t)col0 * K;

    auto copy_stage = [&](int s, int buf) {
        const int k0 = s * 32;
#pragma unroll
        for (int u = 0; u < 4; u++) {
            int idx = u * 256 + tid;
            int row = idx >> 3;
            int c4  = idx & 7;
            uint32_t doff = (uint32_t)((row * LDK + c4 * 4) * 4);
            CP_ASYNC16(as_u32 + buf * (TILE_FLOATS * 4) + doff,
                       Ag + (size_t)row * K + k0 + c4 * 4);
            CP_ASYNC16(bs_u32 + buf * (TILE_FLOATS * 4) + doff,
                       Bg + (size_t)row * K + k0 + c4 * 4);
        }
    };

    float acc[4][4][4];
#pragma unroll
    for (int mt = 0; mt < 4; mt++)
#pragma unroll
        for (int nt = 0; nt < 4; nt++)
#pragma unroll
            for (int r = 0; r < 4; r++) acc[mt][nt][r] = 0.f;

    copy_stage(0, 0);
    CP_COMMIT();

    for (int s = 0; s < NS; s++) {
        const int buf = s & 1;
        if (s + 1 < NS) {
            copy_stage(s + 1, buf ^ 1);
            CP_COMMIT();
            CP_WAIT1();
        } else {
            CP_WAIT0();
        }
        __syncthreads();

        const float* Ab = As + buf * TILE_FLOATS;
        const float* Bb = Bs + buf * TILE_FLOATS;

#pragma unroll
        for (int ks = 0; ks < 4; ks++) {
            const int kk = ks * 8 + t;
            uint32_t af[4][4];
#pragma unroll
            for (int mt = 0; mt < 4; mt++) {
                const float* pa = Ab + (wy * 64 + mt * 16 + g) * LDK + kk;
                af[mt][0] = f2tf32(pa[0]);
                af[mt][1] = f2tf32(pa[8 * LDK]);
                af[mt][2] = f2tf32(pa[4]);
                af[mt][3] = f2tf32(pa[8 * LDK + 4]);
            }
            uint32_t bf[4][2];
#pragma unroll
            for (int nt = 0; nt < 4; nt++) {
                const float* pb = Bb + (wx * 32 + nt * 8 + g) * LDK + kk;
                bf[nt][0] = f2tf32(pb[0]);
                bf[nt][1] = f2tf32(pb[4]);
            }
#pragma unroll
            for (int mt = 0; mt < 4; mt++)
#pragma unroll
                for (int nt = 0; nt < 4; nt++)
                    mma_tf32(acc[mt][nt], af[mt][0], af[mt][1], af[mt][2], af[mt][3],
                             bf[nt][0], bf[nt][1]);
        }
        __syncthreads();
    }

#pragma unroll
    for (int mt = 0; mt < 4; mt++) {
        int m = row0 + wy * 64 + mt * 16 + g;
#pragma unroll
        for (int nt = 0; nt < 4; nt++) {
            int n = col0 + wx * 32 + nt * 8 + 2 * t;
            float2 o0, o1;
            o0.x = acc[mt][nt][0] + bias[n];
            o0.y = acc[mt][nt][1] + bias[n + 1];
            o1.x = acc[mt][nt][2] + bias[n];
            o1.y = acc[mt][nt][3] + bias[n + 1];
            *(float2*)(C + (size_t)m * N + n)       = o0;
            *(float2*)(C + (size_t)(m + 8) * N + n) = o1;
        }
    }
}

// ===========================================================================
// Flash attention with tf32 mma.sync. CTA = (head, 128 q rows), 8 warps.
// Warp w owns q rows [w*16, w*16+16). Per k-block of 128:
//   S = Q@K^T via m16n8k8 (k=d), softmax in accumulator layout,
//   P staged through smem (aliases K tile), O += P@V via m16n8k8 (k=c).
// Smem values pre-rounded to tf32 at load so fragment loads are raw bits.
// ===========================================================================
#define LDQK 68                       // Q/K lead dim  (bank: 4g+t)
#define LDV  72                       // V lead dim    (bank: 8t+g)
#define LDP2 132                      // P lead dim    (bank: 4g+t)
#define AT_KP (128 * LDQK)            // K/P union base (floats)
#define AT_V  (AT_KP + 128 * LDP2)    // V base
#define ATTN_FLOATS (AT_V + 128 * LDV)
#define ATTN_BYTES  (ATTN_FLOATS * 4)

__global__ __launch_bounds__(256)
void attn_mma(const float* __restrict__ qkv, float* __restrict__ out)
{
    extern __shared__ float sm[];
    float* Qs  = sm;               // [128][LDQK]  tf32 values, pre-scaled
    float* KPs = sm + AT_KP;       // Ks [128][LDQK] tf32  |  Ps [128][LDP2] tf32
    float* Vs  = sm + AT_V;        // [128][LDV]   tf32

    const int tid  = threadIdx.x;
    const int lane = tid & 31;
    const int wid  = tid >> 5;
    const int g = lane >> 2;       // 0..7
    const int t = lane & 3;        // 0..3
    const int h  = blockIdx.y;
    const int qb = (int)gridDim.x - 1 - (int)blockIdx.x;   // heavy CTAs first
    const int q0 = qb * 128;
    const int rowbase = wid * 16;  // warp's q-row base (local)

    // ---- load Q tile (tf32-rounded, pre-scaled by 1/8) ----
#pragma unroll
    for (int u = 0; u < 8; u++) {
        int i4 = u * 256 + tid;
        int r = i4 >> 4;
        int d = (i4 & 15) * 4;
        float4 v = *(const float4*)(qkv + (size_t)(q0 + r) * QKVN + h * HD + d);
        float4 w;
        w.x = tf32v(v.x * 0.125f); w.y = tf32v(v.y * 0.125f);
        w.z = tf32v(v.z * 0.125f); w.w = tf32v(v.w * 0.125f);
        *(float4*)&Qs[r * LDQK + d] = w;
    }

    float O[8][4];
    float m0 = -1e30f, m1 = -1e30f, l0 = 0.f, l1 = 0.f;
#pragma unroll
    for (int nt = 0; nt < 8; nt++)
#pragma unroll
        for (int r = 0; r < 4; r++) O[nt][r] = 0.f;

    for (int kb = 0; kb <= qb; kb++) {
        __syncthreads();   // prior P/V consumers done before overwrite

        // ---- load K (tf32) into KPs, V (tf32) into Vs ----
#pragma unroll
        for (int u = 0; u < 8; u++) {
            int i4 = u * 256 + tid;
            int r = i4 >> 4;
            int d = (i4 & 15) * 4;
            const float* base = qkv + (size_t)(kb * 128 + r) * QKVN + h * HD;
            float4 kv = *(const float4*)(base + HID + d);
            float4 vv = *(const float4*)(base + 2 * HID + d);
            float4 kw, vw;
            kw.x = tf32v(kv.x); kw.y = tf32v(kv.y); kw.z = tf32v(kv.z); kw.w = tf32v(kv.w);
            vw.x = tf32v(vv.x); vw.y = tf32v(vv.y); vw.z = tf32v(vv.z); vw.w = tf32v(vv.w);
            *(float4*)&KPs[r * LDQK + d] = kw;
            *(float4*)&Vs[r * LDV + d]   = vw;
        }
        __syncthreads();

        // ---- S = Q @ K^T   (m16 rows x n128 cols, k = d = 64) ----
        float S[16][4];
#pragma unroll
        for (int nt = 0; nt < 16; nt++)
#pragma unroll
            for (int r = 0; r < 4; r++) S[nt][r] = 0.f;

#pragma unroll
        for (int ks = 0; ks < 8; ks++) {
            const float* pa = Qs + (rowbase + g) * LDQK + ks * 8 + t;
            uint32_t a0 = __float_as_uint(pa[0]);
            uint32_t a1 = __float_as_uint(pa[8 * LDQK]);
            uint32_t a2 = __float_as_uint(pa[4]);
            uint32_t a3 = __float_as_uint(pa[8 * LDQK + 4]);
#pragma unroll
            for (int nt = 0; nt < 16; nt++) {
                const float* pb = KPs + (nt * 8 + g) * LDQK + ks * 8 + t;
                uint32_t b0 = __float_as_uint(pb[0]);
                uint32_t b1 = __float_as_uint(pb[4]);
                mma_tf32(S[nt], a0, a1, a2, a3, b0, b1);
            }
        }

        // ---- causal mask on diagonal block ----
        if (kb == qb) {
            const int r0 = rowbase + g, r1 = r0 + 8;
#pragma unroll
            for (int nt = 0; nt < 16; nt++) {
                int c = nt * 8 + 2 * t;
                if (c     > r0) S[nt][0] = -1e30f;
                if (c + 1 > r0) S[nt][1] = -1e30f;
                if (c     > r1) S[nt][2] = -1e30f;
                if (c + 1 > r1) S[nt][3] = -1e30f;
            }
        }

        // ---- online softmax (rows g and g+8, quad-reduced) ----
        float mt0 = -1e30f, mt1 = -1e30f;
#pragma unroll
        for (int nt = 0; nt < 16; nt++) {
            mt0 = fmaxf(mt0, fmaxf(S[nt][0], S[nt][1]));
            mt1 = fmaxf(mt1, fmaxf(S[nt][2], S[nt][3]));
        }
        mt0 = fmaxf(mt0, __shfl_xor_sync(0xffffffffu, mt0, 1));
        mt0 = fmaxf(mt0, __shfl_xor_sync(0xffffffffu, mt0, 2));
        mt1 = fmaxf(mt1, __shfl_xor_sync(0xffffffffu, mt1, 1));
        mt1 = fmaxf(mt1, __shfl_xor_sync(0xffffffffu, mt1, 2));
        float mn0 = fmaxf(m0, mt0), mn1 = fmaxf(m1, mt1);
        float al0 = __expf(m0 - mn0), al1 = __expf(m1 - mn1);
        float ps0 = 0.f, ps1 = 0.f;
#pragma unroll
        for (int nt = 0; nt < 16; nt++) {
            float p00 = __expf(S[nt][0] - mn0);
            float p01 = __expf(S[nt][1] - mn0);
            float p10 = __expf(S[nt][2] - mn1);
            float p11 = __expf(S[nt][3] - mn1);
            S[nt][0] = p00; S[nt][1] = p01; S[nt][2] = p10; S[nt][3] = p11;
            ps0 += p00 + p01;
            ps1 += p10 + p11;
        }
        ps0 += __shfl_xor_sync(0xffffffffu, ps0, 1);
        ps0 += __shfl_xor_sync(0xffffffffu, ps0, 2);
        ps1 += __shfl_xor_sync(0xffffffffu, ps1, 1);
        ps1 += __shfl_xor_sync(0xffffffffu, ps1, 2);
        l0 = l0 * al0 + ps0;  m0 = mn0;
        l1 = l1 * al1 + ps1;  m1 = mn1;
#pragma unroll
        for (int nt = 0; nt < 8; nt++) {
            O[nt][0] *= al0; O[nt][1] *= al0;
            O[nt][2] *= al1; O[nt][3] *= al1;
        }

        __syncthreads();   // all K reads done before P overwrites the union

        // ---- stage P (tf32) into KPs as Ps[128][LDP2] ----
#pragma unroll
        for (int nt = 0; nt < 16; nt++) {
            float2 lo, hi;
            lo.x = tf32v(S[nt][0]); lo.y = tf32v(S[nt][1]);
            hi.x = tf32v(S[nt][2]); hi.y = tf32v(S[nt][3]);
            *(float2*)&KPs[(rowbase + g)     * LDP2 + nt * 8 + 2 * t] = lo;
            *(float2*)&KPs[(rowbase + g + 8) * LDP2 + nt * 8 + 2 * t] = hi;
        }
        __syncthreads();

        // ---- O += P @ V   (k = c = 128, n = d = 64) ----
#pragma unroll
        for (int ks = 0; ks < 16; ks++) {
            const float* pa = KPs + (rowbase + g) * LDP2 + ks * 8 + t;
            uint32_t a0 = __float_as_uint(pa[0]);
            uint32_t a1 = __float_as_uint(pa[8 * LDP2]);
            uint32_t a2 = __float_as_uint(pa[4]);
            uint32_t a3 = __float_as_uint(pa[8 * LDP2 + 4]);
#pragma unroll
            for (int nt = 0; nt < 8; nt++) {
                uint32_t b0 = __float_as_uint(Vs[(ks * 8 + t)     * LDV + nt * 8 + g]);
                uint32_t b1 = __float_as_uint(Vs[(ks * 8 + t + 4) * LDV + nt * 8 + g]);
                mma_tf32(O[nt], a0, a1, a2, a3, b0, b1);
            }
        }
    }

    // ---- epilogue: normalize, write [q][h*64+d] ----
    float inv0 = 1.0f / l0, inv1 = 1.0f / l1;
#pragma unroll
    for (int nt = 0; nt < 8; nt++) {
        int c = h * HD + nt * 8 + 2 * t;
        float2 o0, o1;
        o0.x = O[nt][0] * inv0; o0.y = O[nt][1] * inv0;
        o1.x = O[nt][2] * inv1; o1.y = O[nt][3] * inv1;
        *(float2*)(out + (size_t)(q0 + rowbase + g)     * HID + c) = o0;
        *(float2*)(out + (size_t)(q0 + rowbase + g + 8) * HID + c) = o1;
    }
}

// ---------------------------------------------------------------------------
// Launch
// ---------------------------------------------------------------------------
extern "C" void kernel_launch(void* const* d_in, const int* in_sizes, int n_in,
                              void* d_out, int out_size)
{
    const float* x      = (const float*)d_in[0];
    const float* w_attn = (const float*)d_in[1];
    const float* b_attn = (const float*)d_in[2];
    const float* w_proj = (const float*)d_in[3];
    const float* b_proj = (const float*)d_in[4];
    float* out = (float*)d_out;

    float *qkv_p, *attn_p, *wattnT_p, *wprojT_p;
    cudaGetSymbolAddress((void**)&qkv_p,    g_qkv);
    cudaGetSymbolAddress((void**)&attn_p,   g_attn);
    cudaGetSymbolAddress((void**)&wattnT_p, g_wattnT);
    cudaGetSymbolAddress((void**)&wprojT_p, g_wprojT);

    cudaFuncSetAttribute(attn_mma,
                         cudaFuncAttributeMaxDynamicSharedMemorySize, ATTN_BYTES);
    cudaFuncSetAttribute(gemm_tf32,
                         cudaFuncAttributeMaxDynamicSharedMemorySize, GEMM_SMEM);

    // 0) transpose weights -> K-major operands
    transpose_k<<<dim3(QKVN / 32, HID / 32), 256>>>(w_attn, wattnT_p, HID, QKVN);
    transpose_k<<<dim3(HID / 32, HID / 32), 256>>>(w_proj, wprojT_p, HID, HID);

    // 1) QKV = X @ W_attn + b_attn        [2048, 3072]   (tf32 mma.sync)
    gemm_tf32<<<dim3(QKVN / 128, SEQ / 128), 256, GEMM_SMEM>>>(
        x, wattnT_p, b_attn, qkv_p, SEQ, QKVN, HID);

    // 2) causal flash attention (tf32 mma.sync) -> g_attn [2048, 1024]
    attn_mma<<<dim3(SEQ / 128, NH), 256, ATTN_BYTES>>>(qkv_p, attn_p);

    // 3) out = attn @ W_proj + b_proj     [2048, 1024]   (tf32 mma.sync)
    gemm_tf32<<<dim3(HID / 128, SEQ / 128), 256, GEMM_SMEM>>>(
        attn_p, wprojT_p, b_proj, out, SEQ, HID, HID);
}

// round 7
// speedup vs baseline: 3.4392x; 1.1030x over previous
#include <cuda_runtime.h>
#include <cuda_bf16.h>
#include <cstdint>

// Problem constants
#define SEQ  2048
#define HID  1024
#define NH   16
#define HD   64
#define QKVN (3 * HID)   // 3072

// Scratch (allocation-free rule: __device__ globals)
__device__ float g_qkv[SEQ * QKVN];        // [2048, 3072]
__device__ float g_attn[SEQ * HID];        // [2048, 1024]

// ===========================================================================
// Helpers
// ===========================================================================
__device__ __forceinline__ uint32_t smem_u32(const void* p) {
    uint32_t a;
    asm("{ .reg .u64 t; cvta.to.shared.u64 t, %1; cvt.u32.u64 %0, t; }" : "=r"(a) : "l"(p));
    return a;
}
__device__ __forceinline__ uint32_t f2tf32(float v) {
    uint32_t r;
    asm("cvt.rna.tf32.f32 %0, %1;" : "=r"(r) : "f"(v));
    return r;
}
__device__ __forceinline__ float tf32v(float v) {
    return __uint_as_float(f2tf32(v));
}
__device__ __forceinline__ void mma_tf32(float d[4],
                                         uint32_t a0, uint32_t a1, uint32_t a2, uint32_t a3,
                                         uint32_t b0, uint32_t b1) {
    asm volatile(
        "mma.sync.aligned.m16n8k8.row.col.f32.tf32.tf32.f32 "
        "{%0,%1,%2,%3}, {%4,%5,%6,%7}, {%8,%9}, {%0,%1,%2,%3};"
        : "+f"(d[0]), "+f"(d[1]), "+f"(d[2]), "+f"(d[3])
        : "r"(a0), "r"(a1), "r"(a2), "r"(a3), "r"(b0), "r"(b1));
}
#define CP_ASYNC16(dst_u32, src_ptr) \
    asm volatile("cp.async.cg.shared.global [%0], [%1], 16;" :: "r"(dst_u32), "l"(src_ptr))
#define CP_COMMIT() asm volatile("cp.async.commit_group;" ::: "memory")
#define CP_WAIT1()  asm volatile("cp.async.wait_group 1;" ::: "memory")
#define CP_WAIT0()  asm volatile("cp.async.wait_group 0;" ::: "memory")

// ===========================================================================
// tf32 mma.sync GEMM: C[M,N] = A[M,K] @ B[K,N] + bias[N]   (B row-major)
// CTA 128x128, BK=32, 256 threads (8 warps 2x4), warp 64x32.
// 2-stage double buffer, EXACT control flow of the R4 kernel that passed.
// A smem [128][36], B smem [32][136] (row-major K,N).
// ===========================================================================
#define LDA 36
#define LDB 136
#define A_STAGE (128 * LDA)     // floats
#define B_STAGE (32 * LDB)
#define GEMM_SMEM ((2 * (A_STAGE + B_STAGE)) * 4)

__global__ __launch_bounds__(256)
void gemm_tf32(const float* __restrict__ A, const float* __restrict__ B,
               const float* __restrict__ bias, float* __restrict__ C,
               int M, int N, int K)
{
    extern __shared__ float smem[];
    float* As = smem;                      // [2][A_STAGE]
    float* Bs = smem + 2 * A_STAGE;        // [2][B_STAGE]
    const uint32_t as_u32 = smem_u32(As);
    const uint32_t bs_u32 = smem_u32(Bs);

    const int tid  = threadIdx.x;
    const int wid  = tid >> 5;
    const int lane = tid & 31;
    const int g = lane >> 2;
    const int t = lane & 3;
    const int wy = wid >> 2;                // 0..1
    const int wx = wid & 3;                 // 0..3
    const int row0 = blockIdx.y * 128;
    const int col0 = blockIdx.x * 128;
    const int NS = K >> 5;

    const float* Ag = A + (size_t)row0 * K;
    const float* Bg = B + col0;

    auto copy_stage = [&](int s, int buf) {
        const int k0 = s * 32;
        // A: 128 rows x 8 float4
#pragma unroll
        for (int u = 0; u < 4; u++) {
            int idx = u * 256 + tid;
            int row = idx >> 3;
            int c4  = idx & 7;
            CP_ASYNC16(as_u32 + (buf * A_STAGE + row * LDA + c4 * 4) * 4,
                       Ag + (size_t)row * K + k0 + c4 * 4);
        }
        // B: 32 rows x 32 float4 (row-major K,N)
#pragma unroll
        for (int u = 0; u < 4; u++) {
            int idx = u * 256 + tid;
            int row = idx >> 5;
            int c4  = idx & 31;
            CP_ASYNC16(bs_u32 + (buf * B_STAGE + row * LDB + c4 * 4) * 4,
                       Bg + (size_t)(k0 + row) * N + c4 * 4);
        }
    };

    float acc[4][4][4];
#pragma unroll
    for (int mt = 0; mt < 4; mt++)
#pragma unroll
        for (int nt = 0; nt < 4; nt++)
#pragma unroll
            for (int r = 0; r < 4; r++) acc[mt][nt][r] = 0.f;

    copy_stage(0, 0);
    CP_COMMIT();

    for (int s = 0; s < NS; s++) {
        const int buf = s & 1;
        if (s + 1 < NS) {
            copy_stage(s + 1, buf ^ 1);
            CP_COMMIT();
            CP_WAIT1();
        } else {
            CP_WAIT0();
        }
        __syncthreads();

        const float* Ab = As + buf * A_STAGE;
        const float* Bb = Bs + buf * B_STAGE;

#pragma unroll
        for (int ks = 0; ks < 4; ks++) {
            const int kk = ks * 8;
            uint32_t af[4][4];
#pragma unroll
            for (int mt = 0; mt < 4; mt++) {
                const float* pa = Ab + (wy * 64 + mt * 16 + g) * LDA + kk + t;
                af[mt][0] = f2tf32(pa[0]);
                af[mt][1] = f2tf32(pa[8 * LDA]);
                af[mt][2] = f2tf32(pa[4]);
                af[mt][3] = f2tf32(pa[8 * LDA + 4]);
            }
            uint32_t bf[4][2];
#pragma unroll
            for (int nt = 0; nt < 4; nt++) {
                const float* pb = Bb + (kk + t) * LDB + wx * 32 + nt * 8 + g;
                bf[nt][0] = f2tf32(pb[0]);
                bf[nt][1] = f2tf32(pb[4 * LDB]);
            }
#pragma unroll
            for (int mt = 0; mt < 4; mt++)
#pragma unroll
                for (int nt = 0; nt < 4; nt++)
                    mma_tf32(acc[mt][nt], af[mt][0], af[mt][1], af[mt][2], af[mt][3],
                             bf[nt][0], bf[nt][1]);
        }
        __syncthreads();
    }

#pragma unroll
    for (int mt = 0; mt < 4; mt++) {
        int m = row0 + wy * 64 + mt * 16 + g;
#pragma unroll
        for (int nt = 0; nt < 4; nt++) {
            int n = col0 + wx * 32 + nt * 8 + 2 * t;
            float2 o0, o1;
            o0.x = acc[mt][nt][0] + bias[n];
            o0.y = acc[mt][nt][1] + bias[n + 1];
            o1.x = acc[mt][nt][2] + bias[n];
            o1.y = acc[mt][nt][3] + bias[n + 1];
            *(float2*)(C + (size_t)m * N + n)       = o0;
            *(float2*)(C + (size_t)(m + 8) * N + n) = o1;
        }
    }
}

// ===========================================================================
// Flash attention, tf32 mma.sync. CTA = (head, 64 q rows), 4 warps (128 thr).
// Q held as persistent register fragments. K tile 128 keys, V tile 128.
// P aliases the K smem region. 2 CTAs/SM (70KB smem).
// ===========================================================================
#define ALD 68                       // K lead dim (bank 4g+t)
#define PLD 132                      // P lead dim (bank 4g+t)
#define VLD 72                       // V lead dim (bank 8t+g)
#define KP_FLOATS (128 * ALD)        // union: K[128][68] | P[64][132] | Qstage[64][68]
#define AT_V  KP_FLOATS
#define ATTN_FLOATS (KP_FLOATS + 128 * VLD)
#define ATTN_BYTES  (ATTN_FLOATS * 4)

__global__ __launch_bounds__(128)
void attn_mma(const float* __restrict__ qkv, float* __restrict__ out)
{
    extern __shared__ float sm[];
    float* KPs = sm;               // K / P / Q-stage union
    float* Vs  = sm + AT_V;

    const int tid  = threadIdx.x;
    const int lane = tid & 31;
    const int wid  = tid >> 5;     // 0..3
    const int g = lane >> 2;
    const int t = lane & 3;
    const int h  = blockIdx.y;
    const int qb = (int)gridDim.x - 1 - (int)blockIdx.x;   // heavy CTAs first
    const int q0 = qb * 64;
    const int rowbase = wid * 16;
    const int nkb = (qb >> 1) + 1;

    // ---- stage Q (tf32, pre-scaled) into KPs, then lift to fragments ----
#pragma unroll
    for (int u = 0; u < 8; u++) {
        int i4 = u * 128 + tid;
        int r = i4 >> 4;
        int d = (i4 & 15) * 4;
        float4 v = *(const float4*)(qkv + (size_t)(q0 + r) * QKVN + h * HD + d);
        float4 w;
        w.x = tf32v(v.x * 0.125f); w.y = tf32v(v.y * 0.125f);
        w.z = tf32v(v.z * 0.125f); w.w = tf32v(v.w * 0.125f);
        *(float4*)&KPs[r * ALD + d] = w;
    }
    __syncthreads();

    uint32_t qf[8][4];
#pragma unroll
    for (int ks = 0; ks < 8; ks++) {
        const float* pa = KPs + (rowbase + g) * ALD + ks * 8 + t;
        qf[ks][0] = __float_as_uint(pa[0]);
        qf[ks][1] = __float_as_uint(pa[8 * ALD]);
        qf[ks][2] = __float_as_uint(pa[4]);
        qf[ks][3] = __float_as_uint(pa[8 * ALD + 4]);
    }

    float O[8][4];
    float m0 = -1e30f, m1 = -1e30f, l0 = 0.f, l1 = 0.f;
#pragma unroll
    for (int nt = 0; nt < 8; nt++)
#pragma unroll
        for (int r = 0; r < 4; r++) O[nt][r] = 0.f;

    for (int kb = 0; kb < nkb; kb++) {
        __syncthreads();   // prior consumers of KPs/Vs (and qf reads) done

        // ---- load K (tf32) into KPs, V (tf32) into Vs: 128 rows each ----
#pragma unroll
        for (int u = 0; u < 16; u++) {
            int i4 = u * 128 + tid;
            int r = i4 >> 4;
            int d = (i4 & 15) * 4;
            const float* base = qkv + (size_t)(kb * 128 + r) * QKVN + h * HD;
            float4 kv = *(const float4*)(base + HID + d);
            float4 vv = *(const float4*)(base + 2 * HID + d);
            float4 kw, vw;
            kw.x = tf32v(kv.x); kw.y = tf32v(kv.y); kw.z = tf32v(kv.z); kw.w = tf32v(kv.w);
            vw.x = tf32v(vv.x); vw.y = tf32v(vv.y); vw.z = tf32v(vv.z); vw.w = tf32v(vv.w);
            *(float4*)&KPs[r * ALD + d] = kw;
            *(float4*)&Vs[r * VLD + d]  = vw;
        }
        __syncthreads();

        // ---- S = Q @ K^T ----
        float S[16][4];
#pragma unroll
        for (int nt = 0; nt < 16; nt++)
#pragma unroll
            for (int r = 0; r < 4; r++) S[nt][r] = 0.f;

#pragma unroll
        for (int ks = 0; ks < 8; ks++) {
#pragma unroll
            for (int nt = 0; nt < 16; nt++) {
                const float* pb = KPs + (nt * 8 + g) * ALD + ks * 8 + t;
                uint32_t b0 = __float_as_uint(pb[0]);
                uint32_t b1 = __float_as_uint(pb[4]);
                mma_tf32(S[nt], qf[ks][0], qf[ks][1], qf[ks][2], qf[ks][3], b0, b1);
            }
        }

        // ---- causal mask (last k-block only) ----
        if (kb == nkb - 1) {
            const int r0 = q0 + rowbase + g, r1 = r0 + 8;
            const int cb = kb * 128;
#pragma unroll
            for (int nt = 0; nt < 16; nt++) {
                int c = cb + nt * 8 + 2 * t;
                if (c     > r0) S[nt][0] = -1e30f;
                if (c + 1 > r0) S[nt][1] = -1e30f;
                if (c     > r1) S[nt][2] = -1e30f;
                if (c + 1 > r1) S[nt][3] = -1e30f;
            }
        }

        // ---- online softmax ----
        float mt0 = -1e30f, mt1 = -1e30f;
#pragma unroll
        for (int nt = 0; nt < 16; nt++) {
            mt0 = fmaxf(mt0, fmaxf(S[nt][0], S[nt][1]));
            mt1 = fmaxf(mt1, fmaxf(S[nt][2], S[nt][3]));
        }
        mt0 = fmaxf(mt0, __shfl_xor_sync(0xffffffffu, mt0, 1));
        mt0 = fmaxf(mt0, __shfl_xor_sync(0xffffffffu, mt0, 2));
        mt1 = fmaxf(mt1, __shfl_xor_sync(0xffffffffu, mt1, 1));
        mt1 = fmaxf(mt1, __shfl_xor_sync(0xffffffffu, mt1, 2));
        float mn0 = fmaxf(m0, mt0), mn1 = fmaxf(m1, mt1);
        float al0 = __expf(m0 - mn0), al1 = __expf(m1 - mn1);
        float ps0 = 0.f, ps1 = 0.f;
#pragma unroll
        for (int nt = 0; nt < 16; nt++) {
            float p00 = __expf(S[nt][0] - mn0);
            float p01 = __expf(S[nt][1] - mn0);
            float p10 = __expf(S[nt][2] - mn1);
            float p11 = __expf(S[nt][3] - mn1);
            S[nt][0] = p00; S[nt][1] = p01; S[nt][2] = p10; S[nt][3] = p11;
            ps0 += p00 + p01;
            ps1 += p10 + p11;
        }
        ps0 += __shfl_xor_sync(0xffffffffu, ps0, 1);
        ps0 += __shfl_xor_sync(0xffffffffu, ps0, 2);
        ps1 += __shfl_xor_sync(0xffffffffu, ps1, 1);
        ps1 += __shfl_xor_sync(0xffffffffu, ps1, 2);
        l0 = l0 * al0 + ps0;  m0 = mn0;
        l1 = l1 * al1 + ps1;  m1 = mn1;
#pragma unroll
        for (int nt = 0; nt < 8; nt++) {
            O[nt][0] *= al0; O[nt][1] *= al0;
            O[nt][2] *= al1; O[nt][3] *= al1;
        }

        __syncthreads();   // all K reads done before P overwrites the union

        // ---- stage P (tf32) into KPs as Ps[64][PLD] ----
#pragma unroll
        for (int nt = 0; nt < 16; nt++) {
            float2 lo, hi;
            lo.x = tf32v(S[nt][0]); lo.y = tf32v(S[nt][1]);
            hi.x = tf32v(S[nt][2]); hi.y = tf32v(S[nt][3]);
            *(float2*)&KPs[(rowbase + g)     * PLD + nt * 8 + 2 * t] = lo;
            *(float2*)&KPs[(rowbase + g + 8) * PLD + nt * 8 + 2 * t] = hi;
        }
        __syncthreads();

        // ---- O += P @ V ----
#pragma unroll
        for (int ks = 0; ks < 16; ks++) {
            const float* pa = KPs + (rowbase + g) * PLD + ks * 8 + t;
            uint32_t a0 = __float_as_uint(pa[0]);
            uint32_t a1 = __float_as_uint(pa[8 * PLD]);
            uint32_t a2 = __float_as_uint(pa[4]);
            uint32_t a3 = __float_as_uint(pa[8 * PLD + 4]);
#pragma unroll
            for (int nt = 0; nt < 8; nt++) {
                uint32_t b0 = __float_as_uint(Vs[(ks * 8 + t)     * VLD + nt * 8 + g]);
                uint32_t b1 = __float_as_uint(Vs[(ks * 8 + t + 4) * VLD + nt * 8 + g]);
                mma_tf32(O[nt], a0, a1, a2, a3, b0, b1);
            }
        }
    }

    // ---- epilogue ----
    float inv0 = 1.0f / l0, inv1 = 1.0f / l1;
#pragma unroll
    for (int nt = 0; nt < 8; nt++) {
        int c = h * HD + nt * 8 + 2 * t;
        float2 o0, o1;
        o0.x = O[nt][0] * inv0; o0.y = O[nt][1] * inv0;
        o1.x = O[nt][2] * inv1; o1.y = O[nt][3] * inv1;
        *(float2*)(out + (size_t)(q0 + rowbase + g)     * HID + c) = o0;
        *(float2*)(out + (size_t)(q0 + rowbase + g + 8) * HID + c) = o1;
    }
}

// ---------------------------------------------------------------------------
// Launch
// ---------------------------------------------------------------------------
extern "C" void kernel_launch(void* const* d_in, const int* in_sizes, int n_in,
                              void* d_out, int out_size)
{
    const float* x      = (const float*)d_in[0];
    const float* w_attn = (const float*)d_in[1];
    const float* b_attn = (const float*)d_in[2];
    const float* w_proj = (const float*)d_in[3];
    const float* b_proj = (const float*)d_in[4];
    float* out = (float*)d_out;

    float *qkv_p, *attn_p;
    cudaGetSymbolAddress((void**)&qkv_p,  g_qkv);
    cudaGetSymbolAddress((void**)&attn_p, g_attn);

    cudaFuncSetAttribute(attn_mma,
                         cudaFuncAttributeMaxDynamicSharedMemorySize, ATTN_BYTES);
    cudaFuncSetAttribute(gemm_tf32,
                         cudaFuncAttributeMaxDynamicSharedMemorySize, GEMM_SMEM);

    // 1) QKV = X @ W_attn + b_attn        [2048, 3072]   (tf32 mma.sync, B row-major)
    gemm_tf32<<<dim3(QKVN / 128, SEQ / 128), 256, GEMM_SMEM>>>(
        x, w_attn, b_attn, qkv_p, SEQ, QKVN, HID);

    // 2) causal flash attention (tf32 mma.sync) -> g_attn [2048, 1024]
    attn_mma<<<dim3(SEQ / 64, NH), 128, ATTN_BYTES>>>(qkv_p, attn_p);

    // 3) out = attn @ W_proj + b_proj     [2048, 1024]
    gemm_tf32<<<dim3(HID / 128, SEQ / 128), 256, GEMM_SMEM>>>(
        attn_p, w_proj, b_proj, out, SEQ, HID, HID);
}

// round 8
// speedup vs baseline: 3.5281x; 1.0259x over previous
#include <cuda_runtime.h>
#include <cuda_bf16.h>
#include <cstdint>

// Problem constants
#define SEQ  2048
#define HID  1024
#define NH   16
#define HD   64
#define QKVN (3 * HID)   // 3072

// Scratch (allocation-free rule: __device__ globals)
__device__ float g_qkv[SEQ * QKVN];        // [2048, 3072]  (tf32-rounded values)
__device__ float g_attn[SEQ * HID];        // [2048, 1024]  (tf32-rounded values)
__device__ float g_xr[SEQ * HID];          // x rounded to tf32
__device__ float g_war[HID * QKVN];        // w_attn rounded to tf32
__device__ float g_wpr[HID * HID];         // w_proj rounded to tf32

// ===========================================================================
// Helpers
// ===========================================================================
__device__ __forceinline__ uint32_t smem_u32(const void* p) {
    uint32_t a;
    asm("{ .reg .u64 t; cvta.to.shared.u64 t, %1; cvt.u32.u64 %0, t; }" : "=r"(a) : "l"(p));
    return a;
}
__device__ __forceinline__ uint32_t f2tf32(float v) {
    uint32_t r;
    asm("cvt.rna.tf32.f32 %0, %1;" : "=r"(r) : "f"(v));
    return r;
}
__device__ __forceinline__ float tf32v(float v) {
    return __uint_as_float(f2tf32(v));
}
__device__ __forceinline__ void mma_tf32(float d[4],
                                         uint32_t a0, uint32_t a1, uint32_t a2, uint32_t a3,
                                         uint32_t b0, uint32_t b1) {
    asm volatile(
        "mma.sync.aligned.m16n8k8.row.col.f32.tf32.tf32.f32 "
        "{%0,%1,%2,%3}, {%4,%5,%6,%7}, {%8,%9}, {%0,%1,%2,%3};"
        : "+f"(d[0]), "+f"(d[1]), "+f"(d[2]), "+f"(d[3])
        : "r"(a0), "r"(a1), "r"(a2), "r"(a3), "r"(b0), "r"(b1));
}
#define CP_ASYNC16(dst_u32, src_ptr) \
    asm volatile("cp.async.cg.shared.global [%0], [%1], 16;" :: "r"(dst_u32), "l"(src_ptr))
#define CP_COMMIT() asm volatile("cp.async.commit_group;" ::: "memory")
#define CP_WAIT1()  asm volatile("cp.async.wait_group 1;" ::: "memory")
#define CP_WAIT0()  asm volatile("cp.async.wait_group 0;" ::: "memory")

// ===========================================================================
// Elementwise tf32 rounding pass (run once per call on x / w_attn / w_proj)
// ===========================================================================
__global__ __launch_bounds__(256) void round_tf32(
    const float* __restrict__ in, float* __restrict__ out, int n4)
{
    int i = blockIdx.x * 256 + threadIdx.x;
    if (i < n4) {
        float4 v = *(const float4*)(in + i * 4);
        float4 w;
        w.x = tf32v(v.x); w.y = tf32v(v.y); w.z = tf32v(v.z); w.w = tf32v(v.w);
        *(float4*)(out + i * 4) = w;
    }
}

// ===========================================================================
// tf32 mma.sync GEMM: C[M,N] = A[M,K] @ B[K,N] + bias[N]   (B row-major)
// Inputs MUST already be tf32-rounded values. No cvts in the hot loop.
// CTA 128x128, BK=32, 256 threads (8 warps 2x4), warp 64x32.
// 2-stage double buffer (proven control flow). If round_out, the epilogue
// emits tf32-rounded results (for feeding the next tensor stage).
// ===========================================================================
#define LDA 36
#define LDB 136
#define A_STAGE (128 * LDA)     // floats
#define B_STAGE (32 * LDB)
#define GEMM_SMEM ((2 * (A_STAGE + B_STAGE)) * 4)

__global__ __launch_bounds__(256)
void gemm_tf32(const float* __restrict__ A, const float* __restrict__ B,
               const float* __restrict__ bias, float* __restrict__ C,
               int M, int N, int K, int round_out)
{
    extern __shared__ float smem[];
    float* As = smem;                      // [2][A_STAGE]
    float* Bs = smem + 2 * A_STAGE;        // [2][B_STAGE]
    const uint32_t as_u32 = smem_u32(As);
    const uint32_t bs_u32 = smem_u32(Bs);

    const int tid  = threadIdx.x;
    const int wid  = tid >> 5;
    const int lane = tid & 31;
    const int g = lane >> 2;
    const int t = lane & 3;
    const int wy = wid >> 2;                // 0..1
    const int wx = wid & 3;                 // 0..3
    const int row0 = blockIdx.y * 128;
    const int col0 = blockIdx.x * 128;
    const int NS = K >> 5;

    const float* Ag = A + (size_t)row0 * K;
    const float* Bg = B + col0;

    auto copy_stage = [&](int s, int buf) {
        const int k0 = s * 32;
#pragma unroll
        for (int u = 0; u < 4; u++) {
            int idx = u * 256 + tid;
            int row = idx >> 3;
            int c4  = idx & 7;
            CP_ASYNC16(as_u32 + (buf * A_STAGE + row * LDA + c4 * 4) * 4,
                       Ag + (size_t)row * K + k0 + c4 * 4);
        }
#pragma unroll
        for (int u = 0; u < 4; u++) {
            int idx = u * 256 + tid;
            int row = idx >> 5;
            int c4  = idx & 31;
            CP_ASYNC16(bs_u32 + (buf * B_STAGE + row * LDB + c4 * 4) * 4,
                       Bg + (size_t)(k0 + row) * N + c4 * 4);
        }
    };

    float acc[4][4][4];
#pragma unroll
    for (int mt = 0; mt < 4; mt++)
#pragma unroll
        for (int nt = 0; nt < 4; nt++)
#pragma unroll
            for (int r = 0; r < 4; r++) acc[mt][nt][r] = 0.f;

    copy_stage(0, 0);
    CP_COMMIT();

    for (int s = 0; s < NS; s++) {
        const int buf = s & 1;
        if (s + 1 < NS) {
            copy_stage(s + 1, buf ^ 1);
            CP_COMMIT();
            CP_WAIT1();
        } else {
            CP_WAIT0();
        }
        __syncthreads();

        const float* Ab = As + buf * A_STAGE;
        const float* Bb = Bs + buf * B_STAGE;

#pragma unroll
        for (int ks = 0; ks < 4; ks++) {
            const int kk = ks * 8;
            uint32_t af[4][4];
#pragma unroll
            for (int mt = 0; mt < 4; mt++) {
                const float* pa = Ab + (wy * 64 + mt * 16 + g) * LDA + kk + t;
                af[mt][0] = __float_as_uint(pa[0]);
                af[mt][1] = __float_as_uint(pa[8 * LDA]);
                af[mt][2] = __float_as_uint(pa[4]);
                af[mt][3] = __float_as_uint(pa[8 * LDA + 4]);
            }
            uint32_t bf[4][2];
#pragma unroll
            for (int nt = 0; nt < 4; nt++) {
                const float* pb = Bb + (kk + t) * LDB + wx * 32 + nt * 8 + g;
                bf[nt][0] = __float_as_uint(pb[0]);
                bf[nt][1] = __float_as_uint(pb[4 * LDB]);
            }
#pragma unroll
            for (int mt = 0; mt < 4; mt++)
#pragma unroll
                for (int nt = 0; nt < 4; nt++)
                    mma_tf32(acc[mt][nt], af[mt][0], af[mt][1], af[mt][2], af[mt][3],
                             bf[nt][0], bf[nt][1]);
        }
        __syncthreads();
    }

#pragma unroll
    for (int mt = 0; mt < 4; mt++) {
        int m = row0 + wy * 64 + mt * 16 + g;
#pragma unroll
        for (int nt = 0; nt < 4; nt++) {
            int n = col0 + wx * 32 + nt * 8 + 2 * t;
            float2 o0, o1;
            o0.x = acc[mt][nt][0] + bias[n];
            o0.y = acc[mt][nt][1] + bias[n + 1];
            o1.x = acc[mt][nt][2] + bias[n];
            o1.y = acc[mt][nt][3] + bias[n + 1];
            if (round_out) {
                o0.x = tf32v(o0.x); o0.y = tf32v(o0.y);
                o1.x = tf32v(o1.x); o1.y = tf32v(o1.y);
            }
            *(float2*)(C + (size_t)m * N + n)       = o0;
            *(float2*)(C + (size_t)(m + 8) * N + n) = o1;
        }
    }
}

// ===========================================================================
// Flash attention, tf32 mma.sync. CTA = (head, 64 q rows), 4 warps (128 thr).
// qkv arrives tf32-rounded -> raw float4 smem copies, no cvt in the k-loop.
// Q held as persistent register fragments. P aliases K smem. 2 CTAs/SM.
// ===========================================================================
#define ALD 68                       // K lead dim (bank 4g+t)
#define PLD 132                      // P lead dim (bank 4g+t)
#define VLD 72                       // V lead dim (bank 8t+g)
#define KP_FLOATS (128 * ALD)        // union: K[128][68] | P[64][132] | Qstage[64][68]
#define AT_V  KP_FLOATS
#define ATTN_FLOATS (KP_FLOATS + 128 * VLD)
#define ATTN_BYTES  (ATTN_FLOATS * 4)

__global__ __launch_bounds__(128)
void attn_mma(const float* __restrict__ qkv, float* __restrict__ out)
{
    extern __shared__ float sm[];
    float* KPs = sm;               // K / P / Q-stage union
    float* Vs  = sm + AT_V;

    const int tid  = threadIdx.x;
    const int lane = tid & 31;
    const int wid  = tid >> 5;     // 0..3
    const int g = lane >> 2;
    const int t = lane & 3;
    const int h  = blockIdx.y;
    const int qb = (int)gridDim.x - 1 - (int)blockIdx.x;   // heavy CTAs first
    const int q0 = qb * 64;
    const int rowbase = wid * 16;
    const int nkb = (qb >> 1) + 1;

    // ---- stage Q into KPs (x0.125 is exponent-only: stays valid tf32) ----
#pragma unroll
    for (int u = 0; u < 8; u++) {
        int i4 = u * 128 + tid;
        int r = i4 >> 4;
        int d = (i4 & 15) * 4;
        float4 v = *(const float4*)(qkv + (size_t)(q0 + r) * QKVN + h * HD + d);
        v.x *= 0.125f; v.y *= 0.125f; v.z *= 0.125f; v.w *= 0.125f;
        *(float4*)&KPs[r * ALD + d] = v;
    }
    __syncthreads();

    uint32_t qf[8][4];
#pragma unroll
    for (int ks = 0; ks < 8; ks++) {
        const float* pa = KPs + (rowbase + g) * ALD + ks * 8 + t;
        qf[ks][0] = __float_as_uint(pa[0]);
        qf[ks][1] = __float_as_uint(pa[8 * ALD]);
        qf[ks][2] = __float_as_uint(pa[4]);
        qf[ks][3] = __float_as_uint(pa[8 * ALD + 4]);
    }

    float O[8][4];
    float m0 = -1e30f, m1 = -1e30f, l0 = 0.f, l1 = 0.f;
#pragma unroll
    for (int nt = 0; nt < 8; nt++)
#pragma unroll
        for (int r = 0; r < 4; r++) O[nt][r] = 0.f;

    for (int kb = 0; kb < nkb; kb++) {
        __syncthreads();   // prior consumers of KPs/Vs (and qf reads) done

        // ---- raw copies: K into KPs, V into Vs (values already tf32) ----
#pragma unroll
        for (int u = 0; u < 16; u++) {
            int i4 = u * 128 + tid;
            int r = i4 >> 4;
            int d = (i4 & 15) * 4;
            const float* base = qkv + (size_t)(kb * 128 + r) * QKVN + h * HD;
            *(float4*)&KPs[r * ALD + d] = *(const float4*)(base + HID + d);
            *(float4*)&Vs[r * VLD + d]  = *(const float4*)(base + 2 * HID + d);
        }
        __syncthreads();

        // ---- S = Q @ K^T ----
        float S[16][4];
#pragma unroll
        for (int nt = 0; nt < 16; nt++)
#pragma unroll
            for (int r = 0; r < 4; r++) S[nt][r] = 0.f;

#pragma unroll
        for (int ks = 0; ks < 8; ks++) {
#pragma unroll
            for (int nt = 0; nt < 16; nt++) {
                const float* pb = KPs + (nt * 8 + g) * ALD + ks * 8 + t;
                uint32_t b0 = __float_as_uint(pb[0]);
                uint32_t b1 = __float_as_uint(pb[4]);
                mma_tf32(S[nt], qf[ks][0], qf[ks][1], qf[ks][2], qf[ks][3], b0, b1);
            }
        }

        // ---- causal mask (last k-block only) ----
        if (kb == nkb - 1) {
            const int r0 = q0 + rowbase + g, r1 = r0 + 8;
            const int cb = kb * 128;
#pragma unroll
            for (int nt = 0; nt < 16; nt++) {
                int c = cb + nt * 8 + 2 * t;
                if (c     > r0) S[nt][0] = -1e30f;
                if (c + 1 > r0) S[nt][1] = -1e30f;
                if (c     > r1) S[nt][2] = -1e30f;
                if (c + 1 > r1) S[nt][3] = -1e30f;
            }
        }

        // ---- online softmax ----
        float mt0 = -1e30f, mt1 = -1e30f;
#pragma unroll
        for (int nt = 0; nt < 16; nt++) {
            mt0 = fmaxf(mt0, fmaxf(S[nt][0], S[nt][1]));
            mt1 = fmaxf(mt1, fmaxf(S[nt][2], S[nt][3]));
        }
        mt0 = fmaxf(mt0, __shfl_xor_sync(0xffffffffu, mt0, 1));
        mt0 = fmaxf(mt0, __shfl_xor_sync(0xffffffffu, mt0, 2));
        mt1 = fmaxf(mt1, __shfl_xor_sync(0xffffffffu, mt1, 1));
        mt1 = fmaxf(mt1, __shfl_xor_sync(0xffffffffu, mt1, 2));
        float mn0 = fmaxf(m0, mt0), mn1 = fmaxf(m1, mt1);
        float al0 = __expf(m0 - mn0), al1 = __expf(m1 - mn1);
        float ps0 = 0.f, ps1 = 0.f;
#pragma unroll
        for (int nt = 0; nt < 16; nt++) {
            float p00 = __expf(S[nt][0] - mn0);
            float p01 = __expf(S[nt][1] - mn0);
            float p10 = __expf(S[nt][2] - mn1);
            float p11 = __expf(S[nt][3] - mn1);
            S[nt][0] = p00; S[nt][1] = p01; S[nt][2] = p10; S[nt][3] = p11;
            ps0 += p00 + p01;
            ps1 += p10 + p11;
        }
        ps0 += __shfl_xor_sync(0xffffffffu, ps0, 1);
        ps0 += __shfl_xor_sync(0xffffffffu, ps0, 2);
        ps1 += __shfl_xor_sync(0xffffffffu, ps1, 1);
        ps1 += __shfl_xor_sync(0xffffffffu, ps1, 2);
        l0 = l0 * al0 + ps0;  m0 = mn0;
        l1 = l1 * al1 + ps1;  m1 = mn1;
#pragma unroll
        for (int nt = 0; nt < 8; nt++) {
            O[nt][0] *= al0; O[nt][1] *= al0;
            O[nt][2] *= al1; O[nt][3] *= al1;
        }

        __syncthreads();   // all K reads done before P overwrites the union

        // ---- stage P (tf32) into KPs as Ps[64][PLD] ----
#pragma unroll
        for (int nt = 0; nt < 16; nt++) {
            float2 lo, hi;
            lo.x = tf32v(S[nt][0]); lo.y = tf32v(S[nt][1]);
            hi.x = tf32v(S[nt][2]); hi.y = tf32v(S[nt][3]);
            *(float2*)&KPs[(rowbase + g)     * PLD + nt * 8 + 2 * t] = lo;
            *(float2*)&KPs[(rowbase + g + 8) * PLD + nt * 8 + 2 * t] = hi;
        }
        __syncthreads();

        // ---- O += P @ V ----
#pragma unroll
        for (int ks = 0; ks < 16; ks++) {
            const float* pa = KPs + (rowbase + g) * PLD + ks * 8 + t;
            uint32_t a0 = __float_as_uint(pa[0]);
            uint32_t a1 = __float_as_uint(pa[8 * PLD]);
            uint32_t a2 = __float_as_uint(pa[4]);
            uint32_t a3 = __float_as_uint(pa[8 * PLD + 4]);
#pragma unroll
            for (int nt = 0; nt < 8; nt++) {
                uint32_t b0 = __float_as_uint(Vs[(ks * 8 + t)     * VLD + nt * 8 + g]);
                uint32_t b1 = __float_as_uint(Vs[(ks * 8 + t + 4) * VLD + nt * 8 + g]);
                mma_tf32(O[nt], a0, a1, a2, a3, b0, b1);
            }
        }
    }

    // ---- epilogue: normalize, round to tf32 (feeds proj GEMM) ----
    float inv0 = 1.0f / l0, inv1 = 1.0f / l1;
#pragma unroll
    for (int nt = 0; nt < 8; nt++) {
        int c = h * HD + nt * 8 + 2 * t;
        float2 o0, o1;
        o0.x = tf32v(O[nt][0] * inv0); o0.y = tf32v(O[nt][1] * inv0);
        o1.x = tf32v(O[nt][2] * inv1); o1.y = tf32v(O[nt][3] * inv1);
        *(float2*)(out + (size_t)(q0 + rowbase + g)     * HID + c) = o0;
        *(float2*)(out + (size_t)(q0 + rowbase + g + 8) * HID + c) = o1;
    }
}

// ---------------------------------------------------------------------------
// Launch
// ---------------------------------------------------------------------------
extern "C" void kernel_launch(void* const* d_in, const int* in_sizes, int n_in,
                              void* d_out, int out_size)
{
    const float* x      = (const float*)d_in[0];
    const float* w_attn = (const float*)d_in[1];
    const float* b_attn = (const float*)d_in[2];
    const float* w_proj = (const float*)d_in[3];
    const float* b_proj = (const float*)d_in[4];
    float* out = (float*)d_out;

    float *qkv_p, *attn_p, *xr_p, *war_p, *wpr_p;
    cudaGetSymbolAddress((void**)&qkv_p,  g_qkv);
    cudaGetSymbolAddress((void**)&attn_p, g_attn);
    cudaGetSymbolAddress((void**)&xr_p,   g_xr);
    cudaGetSymbolAddress((void**)&war_p,  g_war);
    cudaGetSymbolAddress((void**)&wpr_p,  g_wpr);

    cudaFuncSetAttribute(attn_mma,
                         cudaFuncAttributeMaxDynamicSharedMemorySize, ATTN_BYTES);
    cudaFuncSetAttribute(gemm_tf32,
                         cudaFuncAttributeMaxDynamicSharedMemorySize, GEMM_SMEM);

    // 0) pre-round inputs to tf32 (once per call)
    round_tf32<<<(SEQ * HID / 4 + 255) / 256, 256>>>(x, xr_p, SEQ * HID / 4);
    round_tf32<<<(HID * QKVN / 4 + 255) / 256, 256>>>(w_attn, war_p, HID * QKVN / 4);
    round_tf32<<<(HID * HID / 4 + 255) / 256, 256>>>(w_proj, wpr_p, HID * HID / 4);

    // 1) QKV = Xr @ W_attn_r + b_attn     [2048, 3072]  (epilogue rounds to tf32)
    gemm_tf32<<<dim3(QKVN / 128, SEQ / 128), 256, GEMM_SMEM>>>(
        xr_p, war_p, b_attn, qkv_p, SEQ, QKVN, HID, 1);

    // 2) causal flash attention -> g_attn [2048, 1024]  (epilogue rounds to tf32)
    attn_mma<<<dim3(SEQ / 64, NH), 128, ATTN_BYTES>>>(qkv_p, attn_p);

    // 3) out = attn @ W_proj_r + b_proj   [2048, 1024]  (no rounding: final)
    gemm_tf32<<<dim3(HID / 128, SEQ / 128), 256, GEMM_SMEM>>>(
        attn_p, wpr_p, b_proj, out, SEQ, HID, HID, 0);
}